// round 2
// baseline (speedup 1.0000x reference)
#include <cuda_runtime.h>
#include <cuda_bf16.h>
#include <math.h>

#define NN 100000
#define EE 1600000
#define DIN 32
#define DOUT 64
#define MAXT 16384

// ---------------- device scratch (static; no allocations allowed) ----------------
__device__ int   d_deg[NN];
__device__ float d_norm[NN];
__device__ int   d_off[NN + 1];
__device__ int   d_cur[NN];
__device__ int   d_csr_src[EE];
__device__ int   d_csr_eid[EE];
__device__ float d_nh[NN * DIN];
__device__ float d_g[NN * DIN];
__device__ float d_hA[NN * DIN];
__device__ float d_hB[NN * DIN];
__device__ unsigned d_keys[EE];
__device__ float d_w[EE];
__device__ unsigned d_hist1[65536];
__device__ unsigned d_hist2[65536];

struct Sel {
    unsigned bucket;
    unsigned R1;
    unsigned T;
    unsigned R2;
    unsigned tieCount;
};
__device__ Sel d_sel;
__device__ int d_tieIdx[MAXT];

// ---------------- kernels ----------------

__global__ void k_deg(const int* __restrict__ dst, int e_n) {
    int e = blockIdx.x * blockDim.x + threadIdx.x;
    if (e < e_n) atomicAdd(&d_deg[dst[e]], 1);
}

__global__ void k_norm(int n) {
    int i = blockIdx.x * blockDim.x + threadIdx.x;
    if (i < n) {
        int dg = d_deg[i];
        if (dg < 1) dg = 1;
        d_norm[i] = rsqrtf((float)dg);
    }
}

// exclusive scan of deg -> off (and cur), single block, shuffle-based
__global__ void k_scan_off(int n) {
    __shared__ int wsum[32];
    __shared__ int s_carry;
    int lane = threadIdx.x & 31, wid = threadIdx.x >> 5;
    if (threadIdx.x == 0) s_carry = 0;
    __syncthreads();
    for (int base = 0; base < n; base += 1024) {
        int i = base + threadIdx.x;
        int v = (i < n) ? d_deg[i] : 0;
        int incl = v;
        #pragma unroll
        for (int o = 1; o < 32; o <<= 1) {
            int t = __shfl_up_sync(0xFFFFFFFFu, incl, o);
            if (lane >= o) incl += t;
        }
        if (lane == 31) wsum[wid] = incl;
        __syncthreads();
        if (wid == 0) {
            int wv = wsum[lane];
            int wi = wv;
            #pragma unroll
            for (int o = 1; o < 32; o <<= 1) {
                int t = __shfl_up_sync(0xFFFFFFFFu, wi, o);
                if (lane >= o) wi += t;
            }
            wsum[lane] = wi - wv;  // exclusive warp offsets
        }
        __syncthreads();
        int total_incl = s_carry + wsum[wid] + incl;
        int ex = total_incl - v;
        if (i < n) { d_off[i] = ex; d_cur[i] = ex; }
        __syncthreads();
        if (threadIdx.x == 1023) s_carry = total_incl;
        __syncthreads();
    }
    if (threadIdx.x == 0) d_off[n] = s_carry;
}

__global__ void k_scatter(const int* __restrict__ src, const int* __restrict__ dst, int e_n) {
    int e = blockIdx.x * blockDim.x + threadIdx.x;
    if (e < e_n) {
        int d = dst[e];
        int p = atomicAdd(&d_cur[d], 1);
        d_csr_src[p] = src[e];
        d_csr_eid[p] = e;
    }
}

// per node: L2-normalized row (nh) and degree-scaled row (g)
__global__ void k_nhg(const float* __restrict__ h, int n) {
    int node = blockIdx.x * (blockDim.x >> 5) + (threadIdx.x >> 5);
    int t = threadIdx.x & 31;
    if (node >= n) return;
    float v = h[node * DIN + t];
    float sq = v * v;
    #pragma unroll
    for (int o = 16; o; o >>= 1) sq += __shfl_xor_sync(0xFFFFFFFFu, sq, o);
    float nrm = sqrtf(sq);
    float inv = 1.0f / fmaxf(nrm, 1e-12f);
    d_nh[node * DIN + t] = v * inv;
    d_g[node * DIN + t]  = v * d_norm[node];
}

// cosine per edge: 8 lanes/edge, float4 loads, shuffle reduce; write sortable key
__global__ void k_cos(const int* __restrict__ src, const int* __restrict__ dst, int e_n) {
    int gid = blockIdx.x * blockDim.x + threadIdx.x;
    int e = gid >> 3;
    int sub = gid & 7;
    if (e >= e_n) return;
    int s = src[e], d = dst[e];
    const float4* nh4 = (const float4*)d_nh;
    float4 a = nh4[s * 8 + sub];
    float4 b = nh4[d * 8 + sub];
    float p = a.x * b.x + a.y * b.y + a.z * b.z + a.w * b.w;
    p += __shfl_xor_sync(0xFFFFFFFFu, p, 1);
    p += __shfl_xor_sync(0xFFFFFFFFu, p, 2);
    p += __shfl_xor_sync(0xFFFFFFFFu, p, 4);
    if (sub == 0) {
        unsigned bits = __float_as_uint(p);
        unsigned key = (bits & 0x80000000u) ? ~bits : (bits | 0x80000000u);
        d_keys[e] = key;
    }
}

__global__ void k_hist1(int e_n) {
    int e = blockIdx.x * blockDim.x + threadIdx.x;
    if (e < e_n) atomicAdd(&d_hist1[d_keys[e] >> 16], 1u);
}

__global__ void k_hist2(int e_n) {
    int e = blockIdx.x * blockDim.x + threadIdx.x;
    if (e < e_n) {
        unsigned key = d_keys[e];
        if ((key >> 16) == d_sel.bucket)
            atomicAdd(&d_hist2[key & 0xFFFFu], 1u);
    }
}

// single block (1024 threads), finds the bucket/value where cumulative count crosses target
__global__ void k_select(int phase, unsigned kcut) {
    const unsigned* hist = phase ? d_hist2 : d_hist1;
    unsigned target = phase ? d_sel.R1 : kcut;
    int base = threadIdx.x * 64;
    unsigned psum = 0;
    #pragma unroll 8
    for (int k = 0; k < 64; k++) psum += hist[base + k];
    int lane = threadIdx.x & 31, wid = threadIdx.x >> 5;
    unsigned incl = psum;
    #pragma unroll
    for (int o = 1; o < 32; o <<= 1) {
        unsigned t = __shfl_up_sync(0xFFFFFFFFu, incl, o);
        if (lane >= o) incl += t;
    }
    __shared__ unsigned wsum[32];
    if (lane == 31) wsum[wid] = incl;
    __syncthreads();
    if (wid == 0) {
        unsigned wv = wsum[lane];
        unsigned wi = wv;
        #pragma unroll
        for (int o = 1; o < 32; o <<= 1) {
            unsigned t = __shfl_up_sync(0xFFFFFFFFu, wi, o);
            if (lane >= o) wi += t;
        }
        wsum[lane] = wi - wv;
    }
    __syncthreads();
    unsigned inclT = wsum[wid] + incl;
    unsigned exclT = inclT - psum;
    if (psum > 0 && exclT < target && target <= inclT) {
        unsigned cum = exclT;
        for (int k = 0; k < 64; k++) {
            unsigned v = hist[base + k];
            if (cum < target && target <= cum + v) {
                if (phase == 0) {
                    d_sel.bucket = (unsigned)(base + k);
                    d_sel.R1 = target - cum;
                } else {
                    d_sel.T = (d_sel.bucket << 16) | (unsigned)(base + k);
                    d_sel.R2 = target - cum;
                }
                break;
            }
            cum += v;
        }
    }
}

__global__ void k_mark(int e_n) {
    int e = blockIdx.x * blockDim.x + threadIdx.x;
    if (e >= e_n) return;
    unsigned key = d_keys[e];
    unsigned T = d_sel.T;
    float w = 1.0f;
    if (key < T) {
        w = 0.0f;
    } else if (key == T) {
        unsigned p = atomicAdd(&d_sel.tieCount, 1u);
        if (p < MAXT) d_tieIdx[p] = e;
    }
    d_w[e] = w;
}

// deterministic tie resolution: cut the R2 ties with smallest edge index
__global__ void k_tie() {
    unsigned M = d_sel.tieCount;
    if (M > MAXT) M = MAXT;
    unsigned R2 = d_sel.R2;
    for (unsigned i = threadIdx.x; i < M; i += blockDim.x) {
        int ei = d_tieIdx[i];
        unsigned rank = 0;
        for (unsigned j = 0; j < M; j++) rank += (unsigned)(d_tieIdx[j] < ei);
        if (rank < R2) d_w[ei] = 0.0f;
    }
}

// propagation: warp per dst node, lane per feature dim, atomic-free via CSR
__global__ void k_prop(float* __restrict__ hout, int n) {
    int node = blockIdx.x * (blockDim.x >> 5) + (threadIdx.x >> 5);
    int t = threadIdx.x & 31;
    if (node >= n) return;
    int b = d_off[node], e2 = d_off[node + 1];
    float acc = 0.0f;
    for (int k = b; k < e2; k++) {
        int s = d_csr_src[k];
        float wgt = d_w[d_csr_eid[k]];
        acc += wgt * d_g[s * DIN + t];
    }
    hout[node * DIN + t] = d_norm[node] * acc;
}

// out[i][j] = sum_t h[i][t] * W[j][t]; 16 rows per block of 1024 threads
__global__ void k_fc(const float* __restrict__ h, const float* __restrict__ W,
                     float* __restrict__ out, int n) {
    __shared__ float sW[DIN * DOUT];   // transposed: sW[t*64 + j]
    __shared__ float sh[16 * DIN];
    for (int i = threadIdx.x; i < DIN * DOUT; i += blockDim.x) {
        int j = i >> 5, t = i & 31;
        sW[t * DOUT + j] = W[i];
    }
    int row0 = blockIdx.x * 16;
    for (int i = threadIdx.x; i < 16 * DIN; i += blockDim.x) {
        int r = row0 + (i >> 5);
        sh[i] = (r < n) ? h[row0 * DIN + i] : 0.0f;
    }
    __syncthreads();
    int r = threadIdx.x >> 6;      // 0..15
    int j = threadIdx.x & 63;      // 0..63
    int row = row0 + r;
    if (row >= n) return;
    float acc = 0.0f;
    #pragma unroll
    for (int t = 0; t < DIN; t++) acc += sh[r * DIN + t] * sW[t * DOUT + j];
    out[row * DOUT + j] = acc;
}

// ---------------- launch ----------------

extern "C" void kernel_launch(void* const* d_in, const int* in_sizes, int n_in,
                              void* d_out, int out_size) {
    const float* features = (const float*)d_in[0];
    const int*   src      = (const int*)d_in[1];
    const int*   dst      = (const int*)d_in[2];
    const float* W        = (const float*)d_in[3];
    float* out = (float*)d_out;

    int n = in_sizes[0] / DIN;
    int e = in_sizes[1];
    if (n > NN) n = NN;
    if (e > EE) e = EE;
    unsigned kcut = (unsigned)((long long)e / 10);

    void *p_deg, *p_h1, *p_h2, *p_sel, *p_hA, *p_hB;
    cudaGetSymbolAddress(&p_deg, d_deg);
    cudaGetSymbolAddress(&p_h1, d_hist1);
    cudaGetSymbolAddress(&p_h2, d_hist2);
    cudaGetSymbolAddress(&p_sel, d_sel);
    cudaGetSymbolAddress(&p_hA, d_hA);
    cudaGetSymbolAddress(&p_hB, d_hB);

    int gE   = (e + 255) / 256;
    int gE8  = (e * 8 + 255) / 256;
    int gN   = (n + 255) / 256;
    int gNw  = (n + 7) / 8;      // warp-per-node blocks of 256

    // degree + norm + CSR (fixed across hops)
    cudaMemsetAsync(p_deg, 0, (size_t)n * sizeof(int));
    k_deg<<<gE, 256>>>(dst, e);
    k_norm<<<gN, 256>>>(n);
    k_scan_off<<<1, 1024>>>(n);
    k_scatter<<<gE, 256>>>(src, dst, e);

    const float* hcur = features;
    float* bufs[2] = {(float*)p_hA, (float*)p_hB};
    for (int hop = 0; hop < 2; hop++) {
        cudaMemsetAsync(p_h1, 0, 65536 * sizeof(unsigned));
        cudaMemsetAsync(p_h2, 0, 65536 * sizeof(unsigned));
        cudaMemsetAsync(p_sel, 0, sizeof(Sel));
        k_nhg<<<gNw, 256>>>(hcur, n);
        k_cos<<<gE8, 256>>>(src, dst, e);
        k_hist1<<<gE, 256>>>(e);
        k_select<<<1, 1024>>>(0, kcut);
        k_hist2<<<gE, 256>>>(e);
        k_select<<<1, 1024>>>(1, kcut);
        k_mark<<<gE, 256>>>(e);
        k_tie<<<1, 256>>>();
        k_prop<<<gNw, 256>>>(bufs[hop], n);
        hcur = bufs[hop];
    }

    k_fc<<<(n + 15) / 16, 1024>>>(hcur, W, out, n);
}

// round 3
// speedup vs baseline: 1.1461x; 1.1461x over previous
#include <cuda_runtime.h>
#include <cuda_bf16.h>
#include <math.h>

#define NN 100000
#define EE 1600000
#define DIN 32
#define DOUT 64
#define MAXT 16384
#define NPART_MAX 128

// ---------------- device scratch ----------------
__device__ int   d_deg[NN];
__device__ float d_norm[NN];
__device__ int   d_off[NN + 1];
__device__ int   d_cur[NN];
__device__ int   d_part[NPART_MAX];
__device__ int   d_csr_src[EE];
__device__ int   d_pos[EE];            // edge -> csr slot (hop-invariant)
__device__ unsigned char d_wc[EE];     // csr-ordered weights (0/1)
__device__ float d_nh[NN * DIN];
__device__ float d_g[NN * DIN];
__device__ float d_hA[NN * DIN];
__device__ float d_hB[NN * DIN];
__device__ unsigned d_keys[EE];

struct SelBlock {
    unsigned hist1[65536];
    unsigned hist2[65536];
    unsigned bucket;
    unsigned R1;
    unsigned T;
    unsigned R2;
    unsigned tieCount;
};
__device__ SelBlock d_sb;
__device__ int d_tieE[MAXT];
__device__ int d_tieP[MAXT];

// ---------------- kernels ----------------

__global__ void k_deg(const int* __restrict__ dst, int e_n) {
    int e = blockIdx.x * blockDim.x + threadIdx.x;
    if (e < e_n) atomicAdd(&d_deg[dst[e]], 1);
}

// phase 1: block sums of deg
__global__ void k_scan_part(int n) {
    int i = blockIdx.x * 1024 + threadIdx.x;
    int v = (i < n) ? d_deg[i] : 0;
    #pragma unroll
    for (int o = 16; o; o >>= 1) v += __shfl_xor_sync(0xFFFFFFFFu, v, o);
    __shared__ int ws[32];
    int lane = threadIdx.x & 31, wid = threadIdx.x >> 5;
    if (lane == 0) ws[wid] = v;
    __syncthreads();
    if (wid == 0) {
        int t = ws[lane];
        #pragma unroll
        for (int o = 16; o; o >>= 1) t += __shfl_xor_sync(0xFFFFFFFFu, t, o);
        if (lane == 0) d_part[blockIdx.x] = t;
    }
}

// phase 2: exclusive scan of block partials (single small block)
__global__ void k_scan_mid(int nb) {
    __shared__ int s[NPART_MAX];
    int t = threadIdx.x;
    int v = (t < nb) ? d_part[t] : 0;
    s[t] = v;
    __syncthreads();
    #pragma unroll
    for (int o = 1; o < NPART_MAX; o <<= 1) {
        int a = (t >= o) ? s[t - o] : 0;
        __syncthreads();
        s[t] += a;
        __syncthreads();
    }
    if (t < nb) d_part[t] = s[t] - v;   // exclusive
}

// phase 3: block-local exclusive scan + base; also writes norm
__global__ void k_scan_fin(int n) {
    int i = blockIdx.x * 1024 + threadIdx.x;
    int lane = threadIdx.x & 31, wid = threadIdx.x >> 5;
    int v = (i < n) ? d_deg[i] : 0;
    int incl = v;
    #pragma unroll
    for (int o = 1; o < 32; o <<= 1) {
        int t = __shfl_up_sync(0xFFFFFFFFu, incl, o);
        if (lane >= o) incl += t;
    }
    __shared__ int ws[32];
    if (lane == 31) ws[wid] = incl;
    __syncthreads();
    if (wid == 0) {
        int wv = ws[lane];
        int wi = wv;
        #pragma unroll
        for (int o = 1; o < 32; o <<= 1) {
            int t = __shfl_up_sync(0xFFFFFFFFu, wi, o);
            if (lane >= o) wi += t;
        }
        ws[lane] = wi - wv;
    }
    __syncthreads();
    int base = d_part[blockIdx.x];
    int incl_blk = ws[wid] + incl;
    int ex = base + incl_blk - v;
    if (i < n) {
        d_off[i] = ex;
        d_cur[i] = ex;
        int dg = v < 1 ? 1 : v;
        d_norm[i] = rsqrtf((float)dg);
    }
    if (i == n - 1) d_off[n] = ex + v;
}

__global__ void k_scatter(const int* __restrict__ src, const int* __restrict__ dst, int e_n) {
    int e = blockIdx.x * blockDim.x + threadIdx.x;
    if (e < e_n) {
        int d = dst[e];
        int p = atomicAdd(&d_cur[d], 1);
        d_csr_src[p] = src[e];
        d_pos[e] = p;                    // coalesced write (by e)
    }
}

// per node: L2-normalized row (nh) and degree-scaled row (g)
__global__ void k_nhg(const float* __restrict__ h, int n) {
    int node = blockIdx.x * (blockDim.x >> 5) + (threadIdx.x >> 5);
    int t = threadIdx.x & 31;
    if (node >= n) return;
    float v = h[node * DIN + t];
    float sq = v * v;
    #pragma unroll
    for (int o = 16; o; o >>= 1) sq += __shfl_xor_sync(0xFFFFFFFFu, sq, o);
    float inv = 1.0f / fmaxf(sqrtf(sq), 1e-12f);
    d_nh[node * DIN + t] = v * inv;
    d_g[node * DIN + t]  = v * d_norm[node];
}

// cosine per edge (8 lanes/edge) + fused hist1
__global__ void k_coshist(const int* __restrict__ src, const int* __restrict__ dst, int e_n) {
    int gid = blockIdx.x * blockDim.x + threadIdx.x;
    int e = gid >> 3;
    int sub = gid & 7;
    if (e >= e_n) return;
    int s = src[e], d = dst[e];
    const float4* nh4 = (const float4*)d_nh;
    float4 a = nh4[s * 8 + sub];
    float4 b = nh4[d * 8 + sub];
    float p = a.x * b.x + a.y * b.y + a.z * b.z + a.w * b.w;
    p += __shfl_xor_sync(0xFFFFFFFFu, p, 1);
    p += __shfl_xor_sync(0xFFFFFFFFu, p, 2);
    p += __shfl_xor_sync(0xFFFFFFFFu, p, 4);
    if (sub == 0) {
        unsigned bits = __float_as_uint(p);
        unsigned key = (bits & 0x80000000u) ? ~bits : (bits | 0x80000000u);
        d_keys[e] = key;
        atomicAdd(&d_sb.hist1[key >> 16], 1u);
    }
}

// second-level histogram (vectorized key read)
__global__ void k_hist2(int e_n) {
    int i = blockIdx.x * blockDim.x + threadIdx.x;
    unsigned bkt = d_sb.bucket;
    int e0 = i * 4;
    if (e0 + 3 < e_n) {
        uint4 kk = ((const uint4*)d_keys)[i];
        if ((kk.x >> 16) == bkt) atomicAdd(&d_sb.hist2[kk.x & 0xFFFFu], 1u);
        if ((kk.y >> 16) == bkt) atomicAdd(&d_sb.hist2[kk.y & 0xFFFFu], 1u);
        if ((kk.z >> 16) == bkt) atomicAdd(&d_sb.hist2[kk.z & 0xFFFFu], 1u);
        if ((kk.w >> 16) == bkt) atomicAdd(&d_sb.hist2[kk.w & 0xFFFFu], 1u);
    } else {
        for (int e = e0; e < e_n; e++) {
            unsigned k = d_keys[e];
            if ((k >> 16) == bkt) atomicAdd(&d_sb.hist2[k & 0xFFFFu], 1u);
        }
    }
}

// single-block selection over 65536-bin histogram
__global__ void k_select(int phase, unsigned kcut) {
    const unsigned* hist = phase ? d_sb.hist2 : d_sb.hist1;
    unsigned target = phase ? d_sb.R1 : kcut;
    int base = threadIdx.x * 64;
    unsigned psum = 0;
    #pragma unroll 8
    for (int k = 0; k < 64; k++) psum += hist[base + k];
    int lane = threadIdx.x & 31, wid = threadIdx.x >> 5;
    unsigned incl = psum;
    #pragma unroll
    for (int o = 1; o < 32; o <<= 1) {
        unsigned t = __shfl_up_sync(0xFFFFFFFFu, incl, o);
        if (lane >= o) incl += t;
    }
    __shared__ unsigned wsum[32];
    if (lane == 31) wsum[wid] = incl;
    __syncthreads();
    if (wid == 0) {
        unsigned wv = wsum[lane];
        unsigned wi = wv;
        #pragma unroll
        for (int o = 1; o < 32; o <<= 1) {
            unsigned t = __shfl_up_sync(0xFFFFFFFFu, wi, o);
            if (lane >= o) wi += t;
        }
        wsum[lane] = wi - wv;
    }
    __syncthreads();
    unsigned inclT = wsum[wid] + incl;
    unsigned exclT = inclT - psum;
    if (psum > 0 && exclT < target && target <= inclT) {
        unsigned cum = exclT;
        for (int k = 0; k < 64; k++) {
            unsigned v = hist[base + k];
            if (cum < target && target <= cum + v) {
                if (phase == 0) {
                    d_sb.bucket = (unsigned)(base + k);
                    d_sb.R1 = target - cum;
                } else {
                    d_sb.T = (d_sb.bucket << 16) | (unsigned)(base + k);
                    d_sb.R2 = target - cum;
                }
                break;
            }
            cum += v;
        }
    }
}

// mark weights into CSR-ordered byte array
__global__ void k_markc(int e_n) {
    int e = blockIdx.x * blockDim.x + threadIdx.x;
    if (e >= e_n) return;
    unsigned key = d_keys[e];
    unsigned T = d_sb.T;
    int p = d_pos[e];
    unsigned char w = 1;
    if (key < T) {
        w = 0;
    } else if (key == T) {
        unsigned q = atomicAdd(&d_sb.tieCount, 1u);
        if (q < MAXT) { d_tieE[q] = e; d_tieP[q] = p; }
    }
    d_wc[p] = w;
}

// deterministic tie resolution: cut R2 ties with smallest edge index
__global__ void k_tie() {
    unsigned M = d_sb.tieCount;
    if (M > MAXT) M = MAXT;
    unsigned R2 = d_sb.R2;
    for (unsigned i = threadIdx.x; i < M; i += blockDim.x) {
        int ei = d_tieE[i];
        unsigned rank = 0;
        for (unsigned j = 0; j < M; j++) rank += (unsigned)(d_tieE[j] < ei);
        if (rank < R2) d_wc[d_tieP[i]] = 0;
    }
}

// propagation: warp per dst node, 4 edges in flight (8 lanes x float4 each)
__global__ void k_prop(float* __restrict__ hout, int n) {
    int node = blockIdx.x * (blockDim.x >> 5) + (threadIdx.x >> 5);
    int t = threadIdx.x & 31;
    if (node >= n) return;
    int b = d_off[node], e2 = d_off[node + 1];
    int g = t >> 3, sub = t & 7;
    float4 acc = make_float4(0.f, 0.f, 0.f, 0.f);
    const float4* g4 = (const float4*)d_g;
    for (int k = b + g; k < e2; k += 4) {
        int s = __ldg(&d_csr_src[k]);
        unsigned char w = d_wc[k];
        if (w) {
            float4 v = g4[s * 8 + sub];
            acc.x += v.x; acc.y += v.y; acc.z += v.z; acc.w += v.w;
        }
    }
    #pragma unroll
    for (int o = 8; o <= 16; o <<= 1) {
        acc.x += __shfl_xor_sync(0xFFFFFFFFu, acc.x, o);
        acc.y += __shfl_xor_sync(0xFFFFFFFFu, acc.y, o);
        acc.z += __shfl_xor_sync(0xFFFFFFFFu, acc.z, o);
        acc.w += __shfl_xor_sync(0xFFFFFFFFu, acc.w, o);
    }
    if (g == 0) {
        float nv = d_norm[node];
        acc.x *= nv; acc.y *= nv; acc.z *= nv; acc.w *= nv;
        ((float4*)hout)[node * 8 + sub] = acc;
    }
}

// out[i][j] = sum_t h[i][t] * W[j][t]
__global__ void k_fc(const float* __restrict__ h, const float* __restrict__ W,
                     float* __restrict__ out, int n) {
    __shared__ float sW[DIN * DOUT];
    __shared__ float sh[16 * DIN];
    for (int i = threadIdx.x; i < DIN * DOUT; i += blockDim.x) {
        int j = i >> 5, t = i & 31;
        sW[t * DOUT + j] = W[i];
    }
    int row0 = blockIdx.x * 16;
    for (int i = threadIdx.x; i < 16 * DIN; i += blockDim.x) {
        int r = row0 + (i >> 5);
        sh[i] = (r < n) ? h[row0 * DIN + i] : 0.0f;
    }
    __syncthreads();
    int r = threadIdx.x >> 6;
    int j = threadIdx.x & 63;
    int row = row0 + r;
    if (row >= n) return;
    float acc = 0.0f;
    #pragma unroll
    for (int t = 0; t < DIN; t++) acc += sh[r * DIN + t] * sW[t * DOUT + j];
    out[row * DOUT + j] = acc;
}

// ---------------- launch ----------------

extern "C" void kernel_launch(void* const* d_in, const int* in_sizes, int n_in,
                              void* d_out, int out_size) {
    const float* features = (const float*)d_in[0];
    const int*   src      = (const int*)d_in[1];
    const int*   dst      = (const int*)d_in[2];
    const float* W        = (const float*)d_in[3];
    float* out = (float*)d_out;

    int n = in_sizes[0] / DIN;
    int e = in_sizes[1];
    if (n > NN) n = NN;
    if (e > EE) e = EE;
    unsigned kcut = (unsigned)((long long)e / 10);

    void *p_deg, *p_sb, *p_hA, *p_hB;
    cudaGetSymbolAddress(&p_deg, d_deg);
    cudaGetSymbolAddress(&p_sb, d_sb);
    cudaGetSymbolAddress(&p_hA, d_hA);
    cudaGetSymbolAddress(&p_hB, d_hB);

    int gE   = (e + 255) / 256;
    int gE8  = (e * 8 + 255) / 256;
    int gE4  = (e / 4 + 255) / 256;
    int gNw  = (n + 7) / 8;
    int nb   = (n + 1023) / 1024;

    cudaMemsetAsync(p_deg, 0, (size_t)n * sizeof(int));
    k_deg<<<gE, 256>>>(dst, e);
    k_scan_part<<<nb, 1024>>>(n);
    k_scan_mid<<<1, NPART_MAX>>>(nb);
    k_scan_fin<<<nb, 1024>>>(n);
    k_scatter<<<gE, 256>>>(src, dst, e);

    const float* hcur = features;
    float* bufs[2] = {(float*)p_hA, (float*)p_hB};
    for (int hop = 0; hop < 2; hop++) {
        cudaMemsetAsync(p_sb, 0, sizeof(SelBlock));
        k_nhg<<<gNw, 256>>>(hcur, n);
        k_coshist<<<gE8, 256>>>(src, dst, e);
        k_select<<<1, 1024>>>(0, kcut);
        k_hist2<<<gE4, 256>>>(e);
        k_select<<<1, 1024>>>(1, kcut);
        k_markc<<<gE, 256>>>(e);
        k_tie<<<1, 256>>>();
        k_prop<<<gNw, 256>>>(bufs[hop], n);
        hcur = bufs[hop];
    }

    k_fc<<<(n + 15) / 16, 1024>>>(hcur, W, out, n);
}

// round 4
// speedup vs baseline: 1.3669x; 1.1926x over previous
#include <cuda_runtime.h>
#include <cuda_bf16.h>
#include <math.h>

#define NN 100000
#define EE 1600000
#define DIN 32
#define DOUT 64
#define MAXT 16384
#define NPART_MAX 128

// ---------------- device scratch ----------------
__device__ int   d_deg[NN];
__device__ float d_norm[NN];
__device__ int   d_off[NN + 1];
__device__ int   d_cur[NN];
__device__ int   d_part[NPART_MAX];
__device__ int   d_csr_src[EE];
__device__ int   d_csr_eid[EE];        // csr slot -> original edge id (tie determinism)
__device__ unsigned char d_wc[EE];     // csr-ordered weights (0/1)
__device__ float d_nh[NN * DIN];
__device__ float d_g[NN * DIN];
__device__ float d_hA[NN * DIN];
__device__ float d_hB[NN * DIN];
__device__ unsigned d_keys[EE];        // csr-ordered sortable keys

struct SelBlock {
    unsigned hist1[65536];
    unsigned hist2[65536];
    unsigned bucket;
    unsigned R1;
    unsigned T;
    unsigned R2;
    unsigned tieCount;
};
__device__ SelBlock d_sb;
__device__ int d_tieE[MAXT];   // original edge ids of ties
__device__ int d_tieP[MAXT];   // csr positions of ties

// ---------------- kernels ----------------

__global__ void k_deg(const int* __restrict__ dst, int e_n) {
    int e = blockIdx.x * blockDim.x + threadIdx.x;
    if (e < e_n) atomicAdd(&d_deg[dst[e]], 1);
}

__global__ void k_scan_part(int n) {
    int i = blockIdx.x * 1024 + threadIdx.x;
    int v = (i < n) ? d_deg[i] : 0;
    #pragma unroll
    for (int o = 16; o; o >>= 1) v += __shfl_xor_sync(0xFFFFFFFFu, v, o);
    __shared__ int ws[32];
    int lane = threadIdx.x & 31, wid = threadIdx.x >> 5;
    if (lane == 0) ws[wid] = v;
    __syncthreads();
    if (wid == 0) {
        int t = ws[lane];
        #pragma unroll
        for (int o = 16; o; o >>= 1) t += __shfl_xor_sync(0xFFFFFFFFu, t, o);
        if (lane == 0) d_part[blockIdx.x] = t;
    }
}

__global__ void k_scan_mid(int nb) {
    __shared__ int s[NPART_MAX];
    int t = threadIdx.x;
    int v = (t < nb) ? d_part[t] : 0;
    s[t] = v;
    __syncthreads();
    #pragma unroll
    for (int o = 1; o < NPART_MAX; o <<= 1) {
        int a = (t >= o) ? s[t - o] : 0;
        __syncthreads();
        s[t] += a;
        __syncthreads();
    }
    if (t < nb) d_part[t] = s[t] - v;
}

__global__ void k_scan_fin(int n) {
    int i = blockIdx.x * 1024 + threadIdx.x;
    int lane = threadIdx.x & 31, wid = threadIdx.x >> 5;
    int v = (i < n) ? d_deg[i] : 0;
    int incl = v;
    #pragma unroll
    for (int o = 1; o < 32; o <<= 1) {
        int t = __shfl_up_sync(0xFFFFFFFFu, incl, o);
        if (lane >= o) incl += t;
    }
    __shared__ int ws[32];
    if (lane == 31) ws[wid] = incl;
    __syncthreads();
    if (wid == 0) {
        int wv = ws[lane];
        int wi = wv;
        #pragma unroll
        for (int o = 1; o < 32; o <<= 1) {
            int t = __shfl_up_sync(0xFFFFFFFFu, wi, o);
            if (lane >= o) wi += t;
        }
        ws[lane] = wi - wv;
    }
    __syncthreads();
    int base = d_part[blockIdx.x];
    int incl_blk = ws[wid] + incl;
    int ex = base + incl_blk - v;
    if (i < n) {
        d_off[i] = ex;
        d_cur[i] = ex;
        int dg = v < 1 ? 1 : v;
        d_norm[i] = rsqrtf((float)dg);
    }
    if (i == n - 1) d_off[n] = ex + v;
}

__global__ void k_scatter(const int* __restrict__ src, const int* __restrict__ dst, int e_n) {
    int e = blockIdx.x * blockDim.x + threadIdx.x;
    if (e < e_n) {
        int d = dst[e];
        int p = atomicAdd(&d_cur[d], 1);
        d_csr_src[p] = src[e];
        d_csr_eid[p] = e;
    }
}

// per node: L2-normalized row (nh) and degree-scaled row (g)
__global__ void k_nhg(const float* __restrict__ h, int n) {
    int node = blockIdx.x * (blockDim.x >> 5) + (threadIdx.x >> 5);
    int t = threadIdx.x & 31;
    if (node >= n) return;
    float v = h[node * DIN + t];
    float sq = v * v;
    #pragma unroll
    for (int o = 16; o; o >>= 1) sq += __shfl_xor_sync(0xFFFFFFFFu, sq, o);
    float inv = 1.0f / fmaxf(sqrtf(sq), 1e-12f);
    d_nh[node * DIN + t] = v * inv;
    d_g[node * DIN + t]  = v * d_norm[node];
}

// cosine in CSR order: warp per dst node; dst row cached in registers;
// 4 edges in flight (8 lanes x float4 per edge). Keys written coalesced.
__global__ void k_cosnode(int n) {
    int node = blockIdx.x * (blockDim.x >> 5) + (threadIdx.x >> 5);
    int t = threadIdx.x & 31;
    if (node >= n) return;
    int g = t >> 3, sub = t & 7;
    const float4* nh4 = (const float4*)d_nh;
    float4 drow = nh4[node * 8 + sub];
    int b = d_off[node], e2 = d_off[node + 1];
    for (int k0 = b; k0 < e2; k0 += 4) {
        int k = k0 + g;
        int valid = (k < e2);
        float p = 0.0f;
        if (valid) {
            int s = __ldg(&d_csr_src[k]);
            float4 a = nh4[s * 8 + sub];
            p = a.x * drow.x + a.y * drow.y + a.z * drow.z + a.w * drow.w;
        }
        p += __shfl_xor_sync(0xFFFFFFFFu, p, 1);
        p += __shfl_xor_sync(0xFFFFFFFFu, p, 2);
        p += __shfl_xor_sync(0xFFFFFFFFu, p, 4);
        if (sub == 0 && valid) {
            unsigned bits = __float_as_uint(p);
            unsigned key = (bits & 0x80000000u) ? ~bits : (bits | 0x80000000u);
            d_keys[k] = key;
        }
    }
}

// level-1 histogram: uint4 reads + warp aggregation (match_any)
__global__ void k_hist1(int e_n) {
    int i = blockIdx.x * blockDim.x + threadIdx.x;
    int e0 = i * 4;
    unsigned b0 = 0, b1 = 0, b2 = 0, b3 = 0;
    int valid = (e0 + 3 < e_n);
    if (valid) {
        uint4 kk = ((const uint4*)d_keys)[i];
        b0 = kk.x >> 16; b1 = kk.y >> 16; b2 = kk.z >> 16; b3 = kk.w >> 16;
    }
    unsigned mask = __ballot_sync(0xFFFFFFFFu, valid);
    if (valid) {
        int lane = threadIdx.x & 31;
        unsigned p;
        p = __match_any_sync(mask, b0);
        if ((__ffs(p) - 1) == lane) atomicAdd(&d_sb.hist1[b0], __popc(p));
        p = __match_any_sync(mask, b1);
        if ((__ffs(p) - 1) == lane) atomicAdd(&d_sb.hist1[b1], __popc(p));
        p = __match_any_sync(mask, b2);
        if ((__ffs(p) - 1) == lane) atomicAdd(&d_sb.hist1[b2], __popc(p));
        p = __match_any_sync(mask, b3);
        if ((__ffs(p) - 1) == lane) atomicAdd(&d_sb.hist1[b3], __popc(p));
    } else {
        for (int e = e0; e < e_n; e++)
            atomicAdd(&d_sb.hist1[d_keys[e] >> 16], 1u);
    }
}

// level-2 histogram: filter by bucket, warp aggregation
__global__ void k_hist2(int e_n) {
    int i = blockIdx.x * blockDim.x + threadIdx.x;
    unsigned bkt = d_sb.bucket;
    int e0 = i * 4;
    int lane = threadIdx.x & 31;
    if (e0 + 3 < e_n) {
        uint4 kk = ((const uint4*)d_keys)[i];
        unsigned k;
        #pragma unroll
        for (int c = 0; c < 4; c++) {
            k = (c == 0) ? kk.x : (c == 1) ? kk.y : (c == 2) ? kk.z : kk.w;
            int hit = ((k >> 16) == bkt);
            unsigned m = __ballot_sync(0xFFFFFFFFu, hit);
            if (hit) {
                unsigned bin = k & 0xFFFFu;
                unsigned p = __match_any_sync(m, bin);
                if ((__ffs(p) - 1) == lane) atomicAdd(&d_sb.hist2[bin], __popc(p));
            }
        }
    } else {
        for (int e = e0; e < e_n; e++) {
            unsigned k = d_keys[e];
            unsigned m = __ballot_sync(__activemask(), (k >> 16) == bkt);
            (void)m;
            if ((k >> 16) == bkt) atomicAdd(&d_sb.hist2[k & 0xFFFFu], 1u);
        }
    }
}

// single-block selection over 65536-bin histogram (uint4 reads)
__global__ void k_select(int phase, unsigned kcut) {
    const unsigned* hist = phase ? d_sb.hist2 : d_sb.hist1;
    unsigned target = phase ? d_sb.R1 : kcut;
    int base = threadIdx.x * 64;
    const uint4* h4 = (const uint4*)(hist + base);
    unsigned psum = 0;
    #pragma unroll
    for (int k = 0; k < 16; k++) {
        uint4 v = h4[k];
        psum += v.x + v.y + v.z + v.w;
    }
    int lane = threadIdx.x & 31, wid = threadIdx.x >> 5;
    unsigned incl = psum;
    #pragma unroll
    for (int o = 1; o < 32; o <<= 1) {
        unsigned t = __shfl_up_sync(0xFFFFFFFFu, incl, o);
        if (lane >= o) incl += t;
    }
    __shared__ unsigned wsum[32];
    if (lane == 31) wsum[wid] = incl;
    __syncthreads();
    if (wid == 0) {
        unsigned wv = wsum[lane];
        unsigned wi = wv;
        #pragma unroll
        for (int o = 1; o < 32; o <<= 1) {
            unsigned t = __shfl_up_sync(0xFFFFFFFFu, wi, o);
            if (lane >= o) wi += t;
        }
        wsum[lane] = wi - wv;
    }
    __syncthreads();
    unsigned inclT = wsum[wid] + incl;
    unsigned exclT = inclT - psum;
    if (psum > 0 && exclT < target && target <= inclT) {
        unsigned cum = exclT;
        for (int k = 0; k < 64; k++) {
            unsigned v = hist[base + k];
            if (cum < target && target <= cum + v) {
                if (phase == 0) {
                    d_sb.bucket = (unsigned)(base + k);
                    d_sb.R1 = target - cum;
                } else {
                    d_sb.T = (d_sb.bucket << 16) | (unsigned)(base + k);
                    d_sb.R2 = target - cum;
                }
                break;
            }
            cum += v;
        }
    }
}

// mark weights, CSR order: fully coalesced byte writes
__global__ void k_markc(int e_n) {
    int k = blockIdx.x * blockDim.x + threadIdx.x;
    if (k >= e_n) return;
    unsigned key = d_keys[k];
    unsigned T = d_sb.T;
    unsigned char w = 1;
    if (key < T) {
        w = 0;
    } else if (key == T) {
        unsigned q = atomicAdd(&d_sb.tieCount, 1u);
        if (q < MAXT) { d_tieE[q] = d_csr_eid[k]; d_tieP[q] = k; }
    }
    d_wc[k] = w;
}

// deterministic tie resolution: cut R2 ties with smallest original edge index
__global__ void k_tie() {
    unsigned M = d_sb.tieCount;
    if (M > MAXT) M = MAXT;
    unsigned R2 = d_sb.R2;
    for (unsigned i = threadIdx.x; i < M; i += blockDim.x) {
        int ei = d_tieE[i];
        unsigned rank = 0;
        for (unsigned j = 0; j < M; j++) rank += (unsigned)(d_tieE[j] < ei);
        if (rank < R2) d_wc[d_tieP[i]] = 0;
    }
}

// propagation: warp per dst node, 4 edges in flight (8 lanes x float4 each)
__global__ void k_prop(float* __restrict__ hout, int n) {
    int node = blockIdx.x * (blockDim.x >> 5) + (threadIdx.x >> 5);
    int t = threadIdx.x & 31;
    if (node >= n) return;
    int b = d_off[node], e2 = d_off[node + 1];
    int g = t >> 3, sub = t & 7;
    float4 acc = make_float4(0.f, 0.f, 0.f, 0.f);
    const float4* g4 = (const float4*)d_g;
    for (int k = b + g; k < e2; k += 4) {
        int s = __ldg(&d_csr_src[k]);
        unsigned char w = d_wc[k];
        if (w) {
            float4 v = g4[s * 8 + sub];
            acc.x += v.x; acc.y += v.y; acc.z += v.z; acc.w += v.w;
        }
    }
    #pragma unroll
    for (int o = 8; o <= 16; o <<= 1) {
        acc.x += __shfl_xor_sync(0xFFFFFFFFu, acc.x, o);
        acc.y += __shfl_xor_sync(0xFFFFFFFFu, acc.y, o);
        acc.z += __shfl_xor_sync(0xFFFFFFFFu, acc.z, o);
        acc.w += __shfl_xor_sync(0xFFFFFFFFu, acc.w, o);
    }
    if (g == 0) {
        float nv = d_norm[node];
        acc.x *= nv; acc.y *= nv; acc.z *= nv; acc.w *= nv;
        ((float4*)hout)[node * 8 + sub] = acc;
    }
}

// out[i][j] = sum_t h[i][t] * W[j][t]
__global__ void k_fc(const float* __restrict__ h, const float* __restrict__ W,
                     float* __restrict__ out, int n) {
    __shared__ float sW[DIN * DOUT];
    __shared__ float sh[16 * DIN];
    for (int i = threadIdx.x; i < DIN * DOUT; i += blockDim.x) {
        int j = i >> 5, t = i & 31;
        sW[t * DOUT + j] = W[i];
    }
    int row0 = blockIdx.x * 16;
    for (int i = threadIdx.x; i < 16 * DIN; i += blockDim.x) {
        int r = row0 + (i >> 5);
        sh[i] = (r < n) ? h[row0 * DIN + i] : 0.0f;
    }
    __syncthreads();
    int r = threadIdx.x >> 6;
    int j = threadIdx.x & 63;
    int row = row0 + r;
    if (row >= n) return;
    float acc = 0.0f;
    #pragma unroll
    for (int t = 0; t < DIN; t++) acc += sh[r * DIN + t] * sW[t * DOUT + j];
    out[row * DOUT + j] = acc;
}

// ---------------- launch ----------------

extern "C" void kernel_launch(void* const* d_in, const int* in_sizes, int n_in,
                              void* d_out, int out_size) {
    const float* features = (const float*)d_in[0];
    const int*   src      = (const int*)d_in[1];
    const int*   dst      = (const int*)d_in[2];
    const float* W        = (const float*)d_in[3];
    float* out = (float*)d_out;

    int n = in_sizes[0] / DIN;
    int e = in_sizes[1];
    if (n > NN) n = NN;
    if (e > EE) e = EE;
    unsigned kcut = (unsigned)((long long)e / 10);

    void *p_deg, *p_sb, *p_hA, *p_hB;
    cudaGetSymbolAddress(&p_deg, d_deg);
    cudaGetSymbolAddress(&p_sb, d_sb);
    cudaGetSymbolAddress(&p_hA, d_hA);
    cudaGetSymbolAddress(&p_hB, d_hB);

    int gE   = (e + 255) / 256;
    int gE4  = (e / 4 + 255) / 256;
    int gNw  = (n + 7) / 8;
    int nb   = (n + 1023) / 1024;

    cudaMemsetAsync(p_deg, 0, (size_t)n * sizeof(int));
    k_deg<<<gE, 256>>>(dst, e);
    k_scan_part<<<nb, 1024>>>(n);
    k_scan_mid<<<1, NPART_MAX>>>(nb);
    k_scan_fin<<<nb, 1024>>>(n);
    k_scatter<<<gE, 256>>>(src, dst, e);

    const float* hcur = features;
    float* bufs[2] = {(float*)p_hA, (float*)p_hB};
    for (int hop = 0; hop < 2; hop++) {
        cudaMemsetAsync(p_sb, 0, sizeof(SelBlock));
        k_nhg<<<gNw, 256>>>(hcur, n);
        k_cosnode<<<gNw, 256>>>(n);
        k_hist1<<<gE4, 256>>>(e);
        k_select<<<1, 1024>>>(0, kcut);
        k_hist2<<<gE4, 256>>>(e);
        k_select<<<1, 1024>>>(1, kcut);
        k_markc<<<gE, 256>>>(e);
        k_tie<<<1, 256>>>();
        k_prop<<<gNw, 256>>>(bufs[hop], n);
        hcur = bufs[hop];
    }

    k_fc<<<(n + 15) / 16, 1024>>>(hcur, W, out, n);
}